// round 3
// baseline (speedup 1.0000x reference)
#include <cuda_runtime.h>
#include <cuda_bf16.h>
#include <mma.h>
#include <math.h>
#include <stdint.h>

using namespace nvcuda;

#define T_STEPS 128
#define BATCH   512
#define HID     512
#define ADIM    18
#define ROWS    (T_STEPS * BATCH)   // 65536
#define NG3     (3 * HID)           // 1536
#define SC_CTAS 96

// ---------------- scratch (static __device__, no allocs) ----------------
__device__ float g_S0[(size_t)ROWS * HID];
__device__ float g_S1[(size_t)ROWS * HID];
__device__ float g_Xg[(size_t)ROWS * NG3];
__device__ float g_Hg[(size_t)BATCH * NG3];
__device__ float g_h  [(size_t)BATCH * HID];   // fp32 carry (exact)
__device__ float g_htf[(size_t)BATCH * HID];   // tf32-RN shadow (GEMM A operand)
__device__ float g_w0c[HID * HID];
__device__ float g_w1c[HID * HID];
__device__ float g_wgc[HID * NG3];
__device__ unsigned int g_bar;                 // monotonic grid barrier

// ---------------- cp.async helpers ----------------
__device__ __forceinline__ void cp16(uint32_t dst, const void* src) {
    asm volatile("cp.async.cg.shared.global [%0], [%1], 16;" :: "r"(dst), "l"(src));
}
#define CP_COMMIT() asm volatile("cp.async.commit_group;")
#define CP_WAIT0()  asm volatile("cp.async.wait_group 0;")
#define CP_WAIT1()  asm volatile("cp.async.wait_group 1;")

// ---------------- tf32-RN conversion passes ----------------
__global__ void conv_tf32(const float* __restrict__ s, float* __restrict__ d, int n4) {
    int i = blockIdx.x * 256 + threadIdx.x;
    if (i < n4) {
        float4 v = ((const float4*)s)[i];
        v.x = wmma::__float_to_tf32(v.x);
        v.y = wmma::__float_to_tf32(v.y);
        v.z = wmma::__float_to_tf32(v.z);
        v.w = wmma::__float_to_tf32(v.w);
        ((float4*)d)[i] = v;
    }
}

// interleave [w_ir | w_iz | w_in] column-wise into [512,1536] tf32
__global__ void conv_gates(const float* __restrict__ wir, const float* __restrict__ wiz,
                           const float* __restrict__ win, float* __restrict__ dst) {
    int i = blockIdx.x * 256 + threadIdx.x;   // 262144
    int k = i >> 9, c = i & 511;
    size_t o = (size_t)k * NG3 + c;
    dst[o]        = wmma::__float_to_tf32(wir[i]);
    dst[o + 512]  = wmma::__float_to_tf32(wiz[i]);
    dst[o + 1024] = wmma::__float_to_tf32(win[i]);
}

// ---------------- double-buffered TF32 GEMM: C[M,N]=A[M,K]@B[K,N] ----------------
// 256 threads, BM=128 BN=128 BK=16, operands pre-rounded tf32 in memory.
__global__ void __launch_bounds__(256, 2) gemm_db(
    const float* __restrict__ A, const float* __restrict__ B,
    float* __restrict__ C, int N, int K)
{
    __shared__ float As[2][128][20];
    __shared__ float Bs[2][16][132];

    const int tid = threadIdx.x;
    const int wid = tid >> 5;
    const size_t m0 = (size_t)blockIdx.y * 128;
    const int n0 = blockIdx.x * 128;
    const int wm = (wid >> 2) * 64;
    const int wn = (wid & 3) * 32;

    wmma::fragment<wmma::accumulator, 16, 16, 8, float> acc[4][2];
#pragma unroll
    for (int i = 0; i < 4; i++)
#pragma unroll
        for (int j = 0; j < 2; j++) wmma::fill_fragment(acc[i][j], 0.0f);

    const int NK = K / 16;

    // per-thread load coords
    const int ar0 = tid >> 2,           ac0 = (tid & 3) * 4;          // A: f=tid
    const int ar1 = (tid + 256) >> 2,   ac1 = ac0;                    // A: f=tid+256
    const int br0 = tid >> 5,           bc0 = (tid & 31) * 4;
    const int br1 = (tid + 256) >> 5,   bc1 = bc0;

    auto load_stage = [&](int kc, int buf) {
        int k0 = kc * 16;
        cp16((uint32_t)__cvta_generic_to_shared(&As[buf][ar0][ac0]), A + (m0 + ar0) * (size_t)K + k0 + ac0);
        cp16((uint32_t)__cvta_generic_to_shared(&As[buf][ar1][ac1]), A + (m0 + ar1) * (size_t)K + k0 + ac1);
        cp16((uint32_t)__cvta_generic_to_shared(&Bs[buf][br0][bc0]), B + (size_t)(k0 + br0) * N + n0 + bc0);
        cp16((uint32_t)__cvta_generic_to_shared(&Bs[buf][br1][bc1]), B + (size_t)(k0 + br1) * N + n0 + bc1);
    };

    load_stage(0, 0);
    CP_COMMIT();

    for (int kc = 0; kc < NK; kc++) {
        int buf = kc & 1;
        if (kc + 1 < NK) { load_stage(kc + 1, buf ^ 1); CP_COMMIT(); CP_WAIT1(); }
        else            { CP_WAIT0(); }
        __syncthreads();
#pragma unroll
        for (int kk = 0; kk < 16; kk += 8) {
            wmma::fragment<wmma::matrix_a, 16, 16, 8, wmma::precision::tf32, wmma::row_major> af[4];
            wmma::fragment<wmma::matrix_b, 16, 16, 8, wmma::precision::tf32, wmma::row_major> bf[2];
#pragma unroll
            for (int i = 0; i < 4; i++) wmma::load_matrix_sync(af[i], &As[buf][wm + 16 * i][kk], 20);
#pragma unroll
            for (int j = 0; j < 2; j++) wmma::load_matrix_sync(bf[j], &Bs[buf][kk][wn + 16 * j], 132);
#pragma unroll
            for (int i = 0; i < 4; i++)
#pragma unroll
                for (int j = 0; j < 2; j++) wmma::mma_sync(acc[i][j], af[i], bf[j], acc[i][j]);
        }
        __syncthreads();
    }
#pragma unroll
    for (int i = 0; i < 4; i++)
#pragma unroll
        for (int j = 0; j < 2; j++)
            wmma::store_matrix_sync(C + (m0 + wm + 16 * i) * (size_t)N + n0 + wn + 16 * j,
                                    acc[i][j], N, wmma::mem_row_major);
}

// ---------------- LayerNorm(+bias,+one-hot) + ReLU, tf32-RN output ----------------
__global__ void __launch_bounds__(128) ln_relu_kernel(
    const float* __restrict__ in, float* __restrict__ out,
    const float* __restrict__ addb,
    const float* __restrict__ lns, const float* __restrict__ lnb,
    const float* __restrict__ w_oh, const int* __restrict__ acts)
{
    const int row = blockIdx.x;
    const int tid = threadIdx.x;
    const float* ip = in + (size_t)row * HID;

    float4 v = *(const float4*)(ip + tid * 4);
    float4 a = *(const float4*)(addb + tid * 4);
    v.x += a.x; v.y += a.y; v.z += a.z; v.w += a.w;
    if (w_oh) {
        const float* oh = w_oh + (size_t)(512 + acts[row]) * HID;
        float4 o = *(const float4*)(oh + tid * 4);
        v.x += o.x; v.y += o.y; v.z += o.z; v.w += o.w;
    }
    float sum = v.x + v.y + v.z + v.w;
    float sq  = v.x * v.x + v.y * v.y + v.z * v.z + v.w * v.w;

    __shared__ float red[8];
#pragma unroll
    for (int off = 16; off > 0; off >>= 1) {
        sum += __shfl_down_sync(0xFFFFFFFFu, sum, off);
        sq  += __shfl_down_sync(0xFFFFFFFFu, sq,  off);
    }
    if ((tid & 31) == 0) { red[tid >> 5] = sum; red[4 + (tid >> 5)] = sq; }
    __syncthreads();
    float ts = red[0] + red[1] + red[2] + red[3];
    float tq = red[4] + red[5] + red[6] + red[7];
    float mean = ts * (1.0f / HID);
    float var  = tq * (1.0f / HID) - mean * mean;
    float inv  = rsqrtf(var + 1e-6f);

    float4 sc = *(const float4*)(lns + tid * 4);
    float4 bb = *(const float4*)(lnb + tid * 4);
    float4 r;
    r.x = wmma::__float_to_tf32(fmaxf((v.x - mean) * inv * sc.x + bb.x, 0.0f));
    r.y = wmma::__float_to_tf32(fmaxf((v.y - mean) * inv * sc.y + bb.y, 0.0f));
    r.z = wmma::__float_to_tf32(fmaxf((v.z - mean) * inv * sc.z + bb.z, 0.0f));
    r.w = wmma::__float_to_tf32(fmaxf((v.w - mean) * inv * sc.w + bb.w, 0.0f));
    *(float4*)(out + (size_t)row * HID + tid * 4) = r;
}

// ---------------- initial done-mask ----------------
__global__ void mask0_kernel(const float* __restrict__ hidden_in,
                             const int* __restrict__ dones)
{
    int i = blockIdx.x * blockDim.x + threadIdx.x;
    int b = i >> 9;
    float v = dones[b] ? 0.0f : hidden_in[i];
    g_h[i] = v;
    g_htf[i] = wmma::__float_to_tf32(v);
}

__device__ __forceinline__ float sigm(float x) { return 1.0f / (1.0f + expf(-x)); }

// ---------------- persistent fused GRU scan ----------------
// 96 CTAs x 256 thr. CTA bx: p = bx % 24 (N-panel of 64), mblk = bx / 24 (M-block of 128).
// Smem: Bp[512][68] weight panel (tf32) + Atile[2][128][20].
__device__ __forceinline__ void gsync() {
    __threadfence();
    __syncthreads();
    if (threadIdx.x == 0) {
        unsigned int old = atomicAdd(&g_bar, 1u);
        unsigned int target = (old / SC_CTAS + 1u) * SC_CTAS;
        while (*((volatile unsigned int*)&g_bar) < target) { }
        __threadfence();
    }
    __syncthreads();
}

__global__ void __launch_bounds__(256, 1) scan_kernel(
    const float* __restrict__ w_hr, const float* __restrict__ w_hz, const float* __restrict__ w_hn,
    const float* __restrict__ b_ir, const float* __restrict__ b_iz,
    const float* __restrict__ b_in, const float* __restrict__ b_hn,
    const int* __restrict__ dones,
    float* __restrict__ out_hidden)
{
    extern __shared__ float ssm[];
    float* Bp = ssm;                       // 512*68
    float* At = ssm + 512 * 68;            // 2*128*20

    const int tid = threadIdx.x;
    const int wid = tid >> 5;
    const int bx  = blockIdx.x;
    const int p   = bx % 24;
    const int mblk = bx / 24;
    const int m0 = mblk * 128;
    const int wsel = p >> 3;
    const int col0 = (p & 7) * 64;
    const int gcol = wsel * 512 + col0;
    const float* W = (wsel == 0) ? w_hr : (wsel == 1 ? w_hz : w_hn);

    // prologue: load weight panel [512 x 64] as tf32-RN
    for (int i4 = tid; i4 < 8192; i4 += 256) {
        int r = i4 >> 4, c4 = (i4 & 15) * 4;
        float4 v = *(const float4*)(W + (size_t)r * HID + col0 + c4);
        float* d = Bp + r * 68 + c4;
        d[0] = wmma::__float_to_tf32(v.x);
        d[1] = wmma::__float_to_tf32(v.y);
        d[2] = wmma::__float_to_tf32(v.z);
        d[3] = wmma::__float_to_tf32(v.w);
    }
    __syncthreads();

    const int ar0 = tid >> 2,         ac0 = (tid & 3) * 4;
    const int ar1 = (tid + 256) >> 2, ac1 = ac0;

    for (int t = 0; t < T_STEPS; t++) {
        // ---- phase G: Hg[m0:m0+128, gcol:gcol+64] = htf @ Wpanel ----
        wmma::fragment<wmma::accumulator, 16, 16, 8, float> acc[4];
#pragma unroll
        for (int j = 0; j < 4; j++) wmma::fill_fragment(acc[j], 0.0f);

        // prefetch chunk 0
        cp16((uint32_t)__cvta_generic_to_shared(At + 0 * 2560 + ar0 * 20 + ac0),
             g_htf + (size_t)(m0 + ar0) * HID + ac0);
        cp16((uint32_t)__cvta_generic_to_shared(At + 0 * 2560 + ar1 * 20 + ac1),
             g_htf + (size_t)(m0 + ar1) * HID + ac1);
        CP_COMMIT();

        const int mrow = wid * 16;
        for (int kc = 0; kc < 32; kc++) {
            int buf = kc & 1;
            if (kc + 1 < 32) {
                int k0n = (kc + 1) * 16;
                cp16((uint32_t)__cvta_generic_to_shared(At + (buf ^ 1) * 2560 + ar0 * 20 + ac0),
                     g_htf + (size_t)(m0 + ar0) * HID + k0n + ac0);
                cp16((uint32_t)__cvta_generic_to_shared(At + (buf ^ 1) * 2560 + ar1 * 20 + ac1),
                     g_htf + (size_t)(m0 + ar1) * HID + k0n + ac1);
                CP_COMMIT(); CP_WAIT1();
            } else CP_WAIT0();
            __syncthreads();
            int k0 = kc * 16;
#pragma unroll
            for (int kk = 0; kk < 16; kk += 8) {
                wmma::fragment<wmma::matrix_a, 16, 16, 8, wmma::precision::tf32, wmma::row_major> af;
                wmma::load_matrix_sync(af, At + buf * 2560 + mrow * 20 + kk, 20);
#pragma unroll
                for (int j = 0; j < 4; j++) {
                    wmma::fragment<wmma::matrix_b, 16, 16, 8, wmma::precision::tf32, wmma::row_major> bf;
                    wmma::load_matrix_sync(bf, Bp + (k0 + kk) * 68 + 16 * j, 68);
                    wmma::mma_sync(acc[j], af, bf, acc[j]);
                }
            }
            __syncthreads();
        }
#pragma unroll
        for (int j = 0; j < 4; j++)
            wmma::store_matrix_sync(g_Hg + (size_t)(m0 + mrow) * NG3 + gcol + 16 * j,
                                    acc[j], NG3, wmma::mem_row_major);
        gsync();

        // ---- phase E: gates ----
        for (int i = bx * 256 + tid; i < BATCH * HID; i += SC_CTAS * 256) {
            int b = i >> 9, c = i & 511;
            const float* xg = g_Xg + ((size_t)t * BATCH + b) * NG3;
            const float* hg = g_Hg + (size_t)b * NG3;
            float r = sigm(__ldcg(xg + c)        + b_ir[c] + __ldcg(hg + c));
            float z = sigm(__ldcg(xg + 512 + c)  + b_iz[c] + __ldcg(hg + 512 + c));
            float n = tanhf(__ldcg(xg + 1024 + c) + b_in[c] + r * (__ldcg(hg + 1024 + c) + b_hn[c]));
            float h = g_h[i];
            float hn = (1.0f - z) * n + z * h;
            g_S0[((size_t)t * BATCH + b) * HID + c] = hn;
            int dn = (t < T_STEPS - 1) ? dones[(t + 1) * BATCH + b] : 0;
            float hm = dn ? 0.0f : hn;
            g_h[i] = hm;
            g_htf[i] = wmma::__float_to_tf32(hm);
            if (t == T_STEPS - 1) out_hidden[i] = hn;
        }
        gsync();
    }
}

// ---------------- output head ----------------
__global__ void __launch_bounds__(256) qout_kernel(
    const float* __restrict__ w_out, const float* __restrict__ b_out,
    float* __restrict__ q)
{
    __shared__ float ws[HID * ADIM];
    for (int i = threadIdx.x; i < HID * ADIM; i += 256) ws[i] = w_out[i];
    __syncthreads();

    const size_t row = (size_t)blockIdx.x * 256 + threadIdx.x;
    const float* y = g_S0 + row * HID;
    float acc[ADIM];
#pragma unroll
    for (int a = 0; a < ADIM; a++) acc[a] = b_out[a];

    for (int c = 0; c < HID; c += 4) {
        float4 v = *(const float4*)(y + c);
        float yv[4] = {v.x, v.y, v.z, v.w};
#pragma unroll
        for (int j = 0; j < 4; j++)
#pragma unroll
            for (int a = 0; a < ADIM; a++)
                acc[a] = fmaf(yv[j], ws[(c + j) * ADIM + a], acc[a]);
    }
    float* qp = q + row * ADIM;
#pragma unroll
    for (int a = 0; a < ADIM; a++) qp[a] = acc[a];
}

// ---------------- launch ----------------
extern "C" void kernel_launch(void* const* d_in, const int* in_sizes, int n_in,
                              void* d_out, int out_size)
{
    const float* hidden    = (const float*)d_in[0];
    const float* obs       = (const float*)d_in[1];
    const int*   dones     = (const int*)d_in[2];
    const int*   last_acts = (const int*)d_in[3];
    const float* w0   = (const float*)d_in[4];
    const float* b0   = (const float*)d_in[5];
    const float* ln0s = (const float*)d_in[6];
    const float* ln0b = (const float*)d_in[7];
    const float* w1   = (const float*)d_in[8];
    const float* b1   = (const float*)d_in[9];
    const float* ln1s = (const float*)d_in[10];
    const float* ln1b = (const float*)d_in[11];
    const float* w_ir = (const float*)d_in[12];
    const float* b_ir = (const float*)d_in[13];
    const float* w_iz = (const float*)d_in[14];
    const float* b_iz = (const float*)d_in[15];
    const float* w_in = (const float*)d_in[16];
    const float* b_in = (const float*)d_in[17];
    const float* w_hr = (const float*)d_in[18];
    const float* w_hz = (const float*)d_in[19];
    const float* w_hn = (const float*)d_in[20];
    const float* b_hn = (const float*)d_in[21];
    const float* w_out = (const float*)d_in[22];
    const float* b_out = (const float*)d_in[23];

    float* out_hidden = (float*)d_out;
    float* out_q      = (float*)d_out + (size_t)BATCH * HID;

    float *S0, *S1, *Xg, *w0c, *w1c, *wgc;
    cudaGetSymbolAddress((void**)&S0,  g_S0);
    cudaGetSymbolAddress((void**)&S1,  g_S1);
    cudaGetSymbolAddress((void**)&Xg,  g_Xg);
    cudaGetSymbolAddress((void**)&w0c, g_w0c);
    cudaGetSymbolAddress((void**)&w1c, g_w1c);
    cudaGetSymbolAddress((void**)&wgc, g_wgc);

    const int scan_smem = (512 * 68 + 2 * 128 * 20) * 4;   // 159744 B
    cudaFuncSetAttribute(scan_kernel, cudaFuncAttributeMaxDynamicSharedMemorySize, scan_smem);

    // pre-round all GEMM operands to tf32-RN
    conv_tf32<<<(ROWS * HID / 4 + 255) / 256, 256>>>(obs, S1, ROWS * HID / 4);
    conv_tf32<<<256, 256>>>(w0, w0c, HID * HID / 4);
    conv_tf32<<<256, 256>>>(w1, w1c, HID * HID / 4);
    conv_gates<<<1024, 256>>>(w_ir, w_iz, w_in, wgc);
    mask0_kernel<<<(BATCH * HID) / 256, 256>>>(hidden, dones);

    // encoder
    gemm_db<<<dim3(4, 512), 256>>>(S1, w0c, S0, HID, HID);
    ln_relu_kernel<<<ROWS, 128>>>(S0, S1, b0, ln0s, ln0b, w0, last_acts);
    gemm_db<<<dim3(4, 512), 256>>>(S1, w1c, S0, HID, HID);
    ln_relu_kernel<<<ROWS, 128>>>(S0, S1, b1, ln1s, ln1b, nullptr, nullptr);
    gemm_db<<<dim3(12, 512), 256>>>(S1, wgc, Xg, NG3, HID);

    // persistent fused GRU scan (one launch, 128 steps)
    scan_kernel<<<SC_CTAS, 256, scan_smem>>>(w_hr, w_hz, w_hn,
                                             b_ir, b_iz, b_in, b_hn,
                                             dones, out_hidden);

    // output head
    qout_kernel<<<ROWS / 256, 256>>>(w_out, b_out, out_q);
}

// round 4
// speedup vs baseline: 1.4236x; 1.4236x over previous
#include <cuda_runtime.h>
#include <cuda_bf16.h>
#include <mma.h>
#include <math.h>
#include <stdint.h>

using namespace nvcuda;

#define T_STEPS 128
#define BATCH   512
#define HID     512
#define ADIM    18
#define ROWS    (T_STEPS * BATCH)   // 65536
#define NG3     (3 * HID)           // 1536
#define SC_CTAS 128

// ---------------- scratch (static __device__, no allocs) ----------------
__device__ float g_S0[(size_t)ROWS * HID];
__device__ float g_S1[(size_t)ROWS * HID];
__device__ float g_Xg[(size_t)ROWS * NG3];
__device__ float g_h  [(size_t)BATCH * HID];   // fp32 carry (exact)
__device__ float g_htf[(size_t)BATCH * HID];   // tf32-RN shadow (GEMM A operand)
__device__ float g_w0c[HID * HID];
__device__ float g_w1c[HID * HID];
__device__ float g_wgc[HID * NG3];
__device__ unsigned int g_bar;                 // monotonic grid barrier

// ---------------- cp.async helpers ----------------
__device__ __forceinline__ void cp16(uint32_t dst, const void* src) {
    asm volatile("cp.async.cg.shared.global [%0], [%1], 16;" :: "r"(dst), "l"(src));
}
#define CP_COMMIT() asm volatile("cp.async.commit_group;")
#define CP_WAIT0()  asm volatile("cp.async.wait_group 0;")
#define CP_WAIT1()  asm volatile("cp.async.wait_group 1;")

__device__ __forceinline__ float tf32r(float x) { return wmma::__float_to_tf32(x); }

__device__ __forceinline__ float tanh_apx(float x) {
    float y;
    asm("tanh.approx.f32 %0, %1;" : "=f"(y) : "f"(x));
    return y;
}
// sigmoid via HW tanh (1 MUFU)
__device__ __forceinline__ float sigm_apx(float x) {
    return 0.5f * tanh_apx(0.5f * x) + 0.5f;
}
// accurate-ish tanh (2 MUFU: EX2 + RCP)
__device__ __forceinline__ float tanh_acc(float v) {
    float e2 = __expf(2.0f * v);
    return 1.0f - __fdividef(2.0f, 1.0f + e2);
}

// ---------------- tf32-RN conversion passes ----------------
__global__ void conv_tf32(const float* __restrict__ s, float* __restrict__ d, int n4) {
    int i = blockIdx.x * 256 + threadIdx.x;
    if (i < n4) {
        float4 v = ((const float4*)s)[i];
        v.x = tf32r(v.x); v.y = tf32r(v.y); v.z = tf32r(v.z); v.w = tf32r(v.w);
        ((float4*)d)[i] = v;
    }
}

// interleave [w_ir | w_iz | w_in] column-wise into [512,1536] tf32
__global__ void conv_gates(const float* __restrict__ wir, const float* __restrict__ wiz,
                           const float* __restrict__ win, float* __restrict__ dst) {
    int i = blockIdx.x * 256 + threadIdx.x;   // 262144
    int k = i >> 9, c = i & 511;
    size_t o = (size_t)k * NG3 + c;
    dst[o]        = tf32r(wir[i]);
    dst[o + 512]  = tf32r(wiz[i]);
    dst[o + 1024] = tf32r(win[i]);
}

// ---------------- double-buffered TF32 GEMM: C[M,N]=A[M,K]@B[K,N] ----------------
__global__ void __launch_bounds__(256, 2) gemm_db(
    const float* __restrict__ A, const float* __restrict__ B,
    float* __restrict__ C, int N, int K)
{
    __shared__ float As[2][128][20];
    __shared__ float Bs[2][16][132];

    const int tid = threadIdx.x;
    const int wid = tid >> 5;
    const size_t m0 = (size_t)blockIdx.y * 128;
    const int n0 = blockIdx.x * 128;
    const int wm = (wid >> 2) * 64;
    const int wn = (wid & 3) * 32;

    wmma::fragment<wmma::accumulator, 16, 16, 8, float> acc[4][2];
#pragma unroll
    for (int i = 0; i < 4; i++)
#pragma unroll
        for (int j = 0; j < 2; j++) wmma::fill_fragment(acc[i][j], 0.0f);

    const int NK = K / 16;

    const int ar0 = tid >> 2,           ac0 = (tid & 3) * 4;
    const int ar1 = (tid + 256) >> 2,   ac1 = ac0;
    const int br0 = tid >> 5,           bc0 = (tid & 31) * 4;
    const int br1 = (tid + 256) >> 5,   bc1 = bc0;

    auto load_stage = [&](int kc, int buf) {
        int k0 = kc * 16;
        cp16((uint32_t)__cvta_generic_to_shared(&As[buf][ar0][ac0]), A + (m0 + ar0) * (size_t)K + k0 + ac0);
        cp16((uint32_t)__cvta_generic_to_shared(&As[buf][ar1][ac1]), A + (m0 + ar1) * (size_t)K + k0 + ac1);
        cp16((uint32_t)__cvta_generic_to_shared(&Bs[buf][br0][bc0]), B + (size_t)(k0 + br0) * N + n0 + bc0);
        cp16((uint32_t)__cvta_generic_to_shared(&Bs[buf][br1][bc1]), B + (size_t)(k0 + br1) * N + n0 + bc1);
    };

    load_stage(0, 0);
    CP_COMMIT();

    for (int kc = 0; kc < NK; kc++) {
        int buf = kc & 1;
        if (kc + 1 < NK) { load_stage(kc + 1, buf ^ 1); CP_COMMIT(); CP_WAIT1(); }
        else            { CP_WAIT0(); }
        __syncthreads();
#pragma unroll
        for (int kk = 0; kk < 16; kk += 8) {
            wmma::fragment<wmma::matrix_a, 16, 16, 8, wmma::precision::tf32, wmma::row_major> af[4];
            wmma::fragment<wmma::matrix_b, 16, 16, 8, wmma::precision::tf32, wmma::row_major> bf[2];
#pragma unroll
            for (int i = 0; i < 4; i++) wmma::load_matrix_sync(af[i], &As[buf][wm + 16 * i][kk], 20);
#pragma unroll
            for (int j = 0; j < 2; j++) wmma::load_matrix_sync(bf[j], &Bs[buf][kk][wn + 16 * j], 132);
#pragma unroll
            for (int i = 0; i < 4; i++)
#pragma unroll
                for (int j = 0; j < 2; j++) wmma::mma_sync(acc[i][j], af[i], bf[j], acc[i][j]);
        }
        __syncthreads();
    }
#pragma unroll
    for (int i = 0; i < 4; i++)
#pragma unroll
        for (int j = 0; j < 2; j++)
            wmma::store_matrix_sync(C + (m0 + wm + 16 * i) * (size_t)N + n0 + wn + 16 * j,
                                    acc[i][j], N, wmma::mem_row_major);
}

// ---------------- LayerNorm(+bias,+one-hot) + ReLU, tf32-RN output ----------------
__global__ void __launch_bounds__(128) ln_relu_kernel(
    const float* __restrict__ in, float* __restrict__ out,
    const float* __restrict__ addb,
    const float* __restrict__ lns, const float* __restrict__ lnb,
    const float* __restrict__ w_oh, const int* __restrict__ acts)
{
    const int row = blockIdx.x;
    const int tid = threadIdx.x;
    const float* ip = in + (size_t)row * HID;

    float4 v = *(const float4*)(ip + tid * 4);
    float4 a = *(const float4*)(addb + tid * 4);
    v.x += a.x; v.y += a.y; v.z += a.z; v.w += a.w;
    if (w_oh) {
        const float* oh = w_oh + (size_t)(512 + acts[row]) * HID;
        float4 o = *(const float4*)(oh + tid * 4);
        v.x += o.x; v.y += o.y; v.z += o.z; v.w += o.w;
    }
    float sum = v.x + v.y + v.z + v.w;
    float sq  = v.x * v.x + v.y * v.y + v.z * v.z + v.w * v.w;

    __shared__ float red[8];
#pragma unroll
    for (int off = 16; off > 0; off >>= 1) {
        sum += __shfl_down_sync(0xFFFFFFFFu, sum, off);
        sq  += __shfl_down_sync(0xFFFFFFFFu, sq,  off);
    }
    if ((tid & 31) == 0) { red[tid >> 5] = sum; red[4 + (tid >> 5)] = sq; }
    __syncthreads();
    float ts = red[0] + red[1] + red[2] + red[3];
    float tq = red[4] + red[5] + red[6] + red[7];
    float mean = ts * (1.0f / HID);
    float var  = tq * (1.0f / HID) - mean * mean;
    float inv  = rsqrtf(var + 1e-6f);

    float4 sc = *(const float4*)(lns + tid * 4);
    float4 bb = *(const float4*)(lnb + tid * 4);
    float4 r;
    r.x = tf32r(fmaxf((v.x - mean) * inv * sc.x + bb.x, 0.0f));
    r.y = tf32r(fmaxf((v.y - mean) * inv * sc.y + bb.y, 0.0f));
    r.z = tf32r(fmaxf((v.z - mean) * inv * sc.z + bb.z, 0.0f));
    r.w = tf32r(fmaxf((v.w - mean) * inv * sc.w + bb.w, 0.0f));
    *(float4*)(out + (size_t)row * HID + tid * 4) = r;
}

// ---------------- initial done-mask ----------------
__global__ void mask0_kernel(const float* __restrict__ hidden_in,
                             const int* __restrict__ dones)
{
    int i = blockIdx.x * blockDim.x + threadIdx.x;
    int b = i >> 9;
    float v = dones[b] ? 0.0f : hidden_in[i];
    g_h[i] = v;
    g_htf[i] = tf32r(v);
}

// ---------------- persistent fused GRU scan ----------------
// 128 CTAs x 256 thr.  bx: cpan = bx&31 (16-col panel), mpan = bx>>5 (128-row panel).
// Each CTA owns h[m0:m0+128, c0:c0+16] and computes r,z,n for that block locally.
// Smem: Wp[3][512][20] weight panels (123KB) + At[2][128][20] (20KB) + Sc[128][52] (27KB).
__device__ __forceinline__ void gsync() {
    __threadfence();
    __syncthreads();
    if (threadIdx.x == 0) {
        unsigned int old = atomicAdd(&g_bar, 1u);
        unsigned int target = (old / SC_CTAS + 1u) * SC_CTAS;
        while (*((volatile unsigned int*)&g_bar) < target) { }
        __threadfence();
    }
    __syncthreads();
}

__global__ void __launch_bounds__(256, 1) scan_kernel(
    const float* __restrict__ w_hr, const float* __restrict__ w_hz, const float* __restrict__ w_hn,
    const float* __restrict__ b_ir, const float* __restrict__ b_iz,
    const float* __restrict__ b_in, const float* __restrict__ b_hn,
    const int* __restrict__ dones,
    float* __restrict__ out_hidden)
{
    extern __shared__ float ssm[];
    float* Wp = ssm;                    // 3 * 512 * 20
    float* At = ssm + 3 * 512 * 20;     // 2 * 128 * 20
    float* Sc = At + 2 * 128 * 20;      // 128 * 52

    const int tid  = threadIdx.x;
    const int wid  = tid >> 5;
    const int lane = tid & 31;
    const int bx   = blockIdx.x;
    const int c0   = (bx & 31) * 16;
    const int m0   = (bx >> 5) * 128;

    // prologue: load 3 weight panels [512 x 16] as tf32-RN
    {
        const float* Ws[3] = {w_hr, w_hz, w_hn};
#pragma unroll
        for (int g = 0; g < 3; g++) {
            for (int i4 = tid; i4 < 2048; i4 += 256) {    // 512*16/4 float4s
                int k = i4 >> 2, cc = (i4 & 3) * 4;
                float4 v = *(const float4*)(Ws[g] + (size_t)k * HID + c0 + cc);
                float* d = Wp + g * (512 * 20) + k * 20 + cc;
                d[0] = tf32r(v.x); d[1] = tf32r(v.y); d[2] = tf32r(v.z); d[3] = tf32r(v.w);
            }
        }
    }
    __syncthreads();

    // A-tile load coords (128 rows x 16 cols per chunk = 512 float4, 2 per thread)
    const int ar0 = tid >> 2,           ac0 = (tid & 3) * 4;
    const int ar1 = (tid + 256) >> 2,   ac1 = ac0;

    const int wrow = wid * 16;          // warp's 16-row slab within the 128

    for (int t = 0; t < T_STEPS; t++) {
        // ---- GEMM: Hg_local[128x16x3] = htf[m0:,:] @ Wp ----
        wmma::fragment<wmma::accumulator, 16, 16, 8, float> acc[3];
#pragma unroll
        for (int g = 0; g < 3; g++) wmma::fill_fragment(acc[g], 0.0f);

        cp16((uint32_t)__cvta_generic_to_shared(At + ar0 * 20 + ac0),
             g_htf + (size_t)(m0 + ar0) * HID + ac0);
        cp16((uint32_t)__cvta_generic_to_shared(At + ar1 * 20 + ac1),
             g_htf + (size_t)(m0 + ar1) * HID + ac1);
        CP_COMMIT();

        for (int kc = 0; kc < 32; kc++) {
            int buf = kc & 1;
            if (kc + 1 < 32) {
                int k0n = (kc + 1) * 16;
                cp16((uint32_t)__cvta_generic_to_shared(At + (buf ^ 1) * 2560 + ar0 * 20 + ac0),
                     g_htf + (size_t)(m0 + ar0) * HID + k0n + ac0);
                cp16((uint32_t)__cvta_generic_to_shared(At + (buf ^ 1) * 2560 + ar1 * 20 + ac1),
                     g_htf + (size_t)(m0 + ar1) * HID + k0n + ac1);
                CP_COMMIT(); CP_WAIT1();
            } else CP_WAIT0();
            __syncthreads();
            int k0 = kc * 16;
#pragma unroll
            for (int kk = 0; kk < 16; kk += 8) {
                wmma::fragment<wmma::matrix_a, 16, 16, 8, wmma::precision::tf32, wmma::row_major> af;
                wmma::load_matrix_sync(af, At + buf * 2560 + wrow * 20 + kk, 20);
#pragma unroll
                for (int g = 0; g < 3; g++) {
                    wmma::fragment<wmma::matrix_b, 16, 16, 8, wmma::precision::tf32, wmma::row_major> bf;
                    wmma::load_matrix_sync(bf, Wp + g * (512 * 20) + (k0 + kk) * 20, 20);
                    wmma::mma_sync(acc[g], af, bf, acc[g]);
                }
            }
            __syncthreads();
        }

        // spill accumulators to this warp's scratch slab: r at col 0, z at 16, n at 32
#pragma unroll
        for (int g = 0; g < 3; g++)
            wmma::store_matrix_sync(Sc + wrow * 52 + g * 16, acc[g], 52, wmma::mem_row_major);
        __syncwarp();

        // ---- gates: local, no grid barrier needed ----
        const bool lastt = (t == T_STEPS - 1);
#pragma unroll
        for (int j = 0; j < 8; j++) {
            int e = j * 32 + lane;            // 256 elements = 16 rows x 16 cols
            int row = e >> 4, col = e & 15;
            int bg = m0 + wrow + row;
            int cg = c0 + col;
            const float* sc = Sc + (wrow + row) * 52 + col;
            float hgr = sc[0], hgz = sc[16], hgn = sc[32];
            const float* xg = g_Xg + ((size_t)t * BATCH + bg) * NG3 + cg;
            float xr = __ldcg(xg), xz = __ldcg(xg + 512), xn = __ldcg(xg + 1024);
            float r = sigm_apx(xr + __ldg(b_ir + cg) + hgr);
            float z = sigm_apx(xz + __ldg(b_iz + cg) + hgz);
            float n = tanh_acc(xn + __ldg(b_in + cg) + r * (hgn + __ldg(b_hn + cg)));
            size_t hi = (size_t)bg * HID + cg;
            float h = g_h[hi];
            float hn = (1.0f - z) * n + z * h;
            g_S0[((size_t)t * BATCH + bg) * HID + cg] = hn;
            int dn = lastt ? 0 : dones[(t + 1) * BATCH + bg];
            float hm = dn ? 0.0f : hn;
            g_h[hi] = hm;
            g_htf[hi] = tf32r(hm);
            if (lastt) out_hidden[hi] = hn;
        }

        gsync();   // one barrier per step: publish htf before next step's GEMM
    }
}

// ---------------- output head ----------------
__global__ void __launch_bounds__(256) qout_kernel(
    const float* __restrict__ w_out, const float* __restrict__ b_out,
    float* __restrict__ q)
{
    __shared__ float ws[HID * ADIM];
    for (int i = threadIdx.x; i < HID * ADIM; i += 256) ws[i] = w_out[i];
    __syncthreads();

    const size_t row = (size_t)blockIdx.x * 256 + threadIdx.x;
    const float* y = g_S0 + row * HID;
    float acc[ADIM];
#pragma unroll
    for (int a = 0; a < ADIM; a++) acc[a] = b_out[a];

    for (int c = 0; c < HID; c += 4) {
        float4 v = *(const float4*)(y + c);
        float yv[4] = {v.x, v.y, v.z, v.w};
#pragma unroll
        for (int j = 0; j < 4; j++)
#pragma unroll
            for (int a = 0; a < ADIM; a++)
                acc[a] = fmaf(yv[j], ws[(c + j) * ADIM + a], acc[a]);
    }
    float* qp = q + row * ADIM;
#pragma unroll
    for (int a = 0; a < ADIM; a++) qp[a] = acc[a];
}

// ---------------- launch ----------------
extern "C" void kernel_launch(void* const* d_in, const int* in_sizes, int n_in,
                              void* d_out, int out_size)
{
    const float* hidden    = (const float*)d_in[0];
    const float* obs       = (const float*)d_in[1];
    const int*   dones     = (const int*)d_in[2];
    const int*   last_acts = (const int*)d_in[3];
    const float* w0   = (const float*)d_in[4];
    const float* b0   = (const float*)d_in[5];
    const float* ln0s = (const float*)d_in[6];
    const float* ln0b = (const float*)d_in[7];
    const float* w1   = (const float*)d_in[8];
    const float* b1   = (const float*)d_in[9];
    const float* ln1s = (const float*)d_in[10];
    const float* ln1b = (const float*)d_in[11];
    const float* w_ir = (const float*)d_in[12];
    const float* b_ir = (const float*)d_in[13];
    const float* w_iz = (const float*)d_in[14];
    const float* b_iz = (const float*)d_in[15];
    const float* w_in = (const float*)d_in[16];
    const float* b_in = (const float*)d_in[17];
    const float* w_hr = (const float*)d_in[18];
    const float* w_hz = (const float*)d_in[19];
    const float* w_hn = (const float*)d_in[20];
    const float* b_hn = (const float*)d_in[21];
    const float* w_out = (const float*)d_in[22];
    const float* b_out = (const float*)d_in[23];

    float* out_hidden = (float*)d_out;
    float* out_q      = (float*)d_out + (size_t)BATCH * HID;

    float *S0, *S1, *Xg, *w0c, *w1c, *wgc;
    cudaGetSymbolAddress((void**)&S0,  g_S0);
    cudaGetSymbolAddress((void**)&S1,  g_S1);
    cudaGetSymbolAddress((void**)&Xg,  g_Xg);
    cudaGetSymbolAddress((void**)&w0c, g_w0c);
    cudaGetSymbolAddress((void**)&w1c, g_w1c);
    cudaGetSymbolAddress((void**)&wgc, g_wgc);

    const int scan_smem = (3 * 512 * 20 + 2 * 128 * 20 + 128 * 52) * 4;   // 169984 B
    cudaFuncSetAttribute(scan_kernel, cudaFuncAttributeMaxDynamicSharedMemorySize, scan_smem);

    // pre-round all GEMM operands to tf32-RN
    conv_tf32<<<(ROWS * HID / 4 + 255) / 256, 256>>>(obs, S1, ROWS * HID / 4);
    conv_tf32<<<256, 256>>>(w0, w0c, HID * HID / 4);
    conv_tf32<<<256, 256>>>(w1, w1c, HID * HID / 4);
    conv_gates<<<1024, 256>>>(w_ir, w_iz, w_in, wgc);
    mask0_kernel<<<(BATCH * HID) / 256, 256>>>(hidden, dones);

    // encoder
    gemm_db<<<dim3(4, 512), 256>>>(S1, w0c, S0, HID, HID);
    ln_relu_kernel<<<ROWS, 128>>>(S0, S1, b0, ln0s, ln0b, w0, last_acts);
    gemm_db<<<dim3(4, 512), 256>>>(S1, w1c, S0, HID, HID);
    ln_relu_kernel<<<ROWS, 128>>>(S0, S1, b1, ln1s, ln1b, nullptr, nullptr);
    gemm_db<<<dim3(12, 512), 256>>>(S1, wgc, Xg, NG3, HID);

    // persistent fused GRU scan (one launch, 128 steps, 1 barrier/step)
    scan_kernel<<<SC_CTAS, 256, scan_smem>>>(w_hr, w_hz, w_hn,
                                             b_ir, b_iz, b_in, b_hn,
                                             dones, out_hidden);

    // output head
    qout_kernel<<<ROWS / 256, 256>>>(w_out, b_out, out_q);
}

// round 5
// speedup vs baseline: 1.4615x; 1.0266x over previous
#include <cuda_runtime.h>
#include <cuda_bf16.h>
#include <mma.h>
#include <math.h>
#include <stdint.h>

using namespace nvcuda;

#define T_STEPS 128
#define BATCH   512
#define HID     512
#define ADIM    18
#define ROWS    (T_STEPS * BATCH)   // 65536
#define NG3     (3 * HID)           // 1536
#define SC_CTAS 128

// ---------------- scratch (static __device__, no allocs) ----------------
__device__ float g_S0[(size_t)ROWS * HID];
__device__ float g_S1[(size_t)ROWS * HID];
__device__ float g_Xg[(size_t)ROWS * NG3];
__device__ float g_h  [(size_t)BATCH * HID];   // fp32 carry (exact)
__device__ float g_htf[(size_t)BATCH * HID];   // tf32-RN shadow (GEMM A operand)
__device__ float g_w0c[HID * HID];
__device__ float g_w1c[HID * HID];
__device__ float g_wgc[HID * NG3];
__device__ unsigned int g_bar;                 // monotonic grid barrier

// ---------------- cp.async helpers ----------------
__device__ __forceinline__ void cp16(uint32_t dst, const void* src) {
    asm volatile("cp.async.cg.shared.global [%0], [%1], 16;" :: "r"(dst), "l"(src));
}
#define CP_COMMIT() asm volatile("cp.async.commit_group;")
#define CP_WAIT0()  asm volatile("cp.async.wait_group 0;")
#define CP_WAIT1()  asm volatile("cp.async.wait_group 1;")

__device__ __forceinline__ float tf32r(float x) { return wmma::__float_to_tf32(x); }

__device__ __forceinline__ float tanh_apx(float x) {
    float y;
    asm("tanh.approx.f32 %0, %1;" : "=f"(y) : "f"(x));
    return y;
}
__device__ __forceinline__ float sigm_apx(float x) {
    return 0.5f * tanh_apx(0.5f * x) + 0.5f;
}
__device__ __forceinline__ float tanh_acc(float v) {
    float e2 = __expf(2.0f * v);
    return 1.0f - __fdividef(2.0f, 1.0f + e2);
}

// ---------------- tf32-RN conversion passes ----------------
__global__ void conv_tf32(const float* __restrict__ s, float* __restrict__ d, int n4) {
    int i = blockIdx.x * 256 + threadIdx.x;
    if (i < n4) {
        float4 v = ((const float4*)s)[i];
        v.x = tf32r(v.x); v.y = tf32r(v.y); v.z = tf32r(v.z); v.w = tf32r(v.w);
        ((float4*)d)[i] = v;
    }
}

// interleave [w_ir | w_iz | w_in] column-wise into [512,1536] tf32
__global__ void conv_gates(const float* __restrict__ wir, const float* __restrict__ wiz,
                           const float* __restrict__ win, float* __restrict__ dst) {
    int i = blockIdx.x * 256 + threadIdx.x;   // 262144
    int k = i >> 9, c = i & 511;
    size_t o = (size_t)k * NG3 + c;
    dst[o]        = tf32r(wir[i]);
    dst[o + 512]  = tf32r(wiz[i]);
    dst[o + 1024] = tf32r(win[i]);
}

// ---------------- double-buffered TF32 GEMM v2: BK=32 ----------------
// 256 threads, BM=128 BN=128 BK=32, dynamic smem, 2 CTA/SM.
#define GA_LD 36
#define GB_LD 132
#define GA_SZ (128 * GA_LD)       // 4608 floats / stage
#define GB_SZ (32 * GB_LD)        // 4224 floats / stage

__global__ void __launch_bounds__(256, 2) gemm_db(
    const float* __restrict__ A, const float* __restrict__ B,
    float* __restrict__ C, int N, int K)
{
    extern __shared__ float sm[];
    float* As = sm;                         // 2 stages x GA_SZ
    float* Bs = sm + 2 * GA_SZ;             // 2 stages x GB_SZ

    const int tid = threadIdx.x;
    const int wid = tid >> 5;
    const size_t m0 = (size_t)blockIdx.y * 128;
    const int n0 = blockIdx.x * 128;
    const int wm = (wid >> 2) * 64;
    const int wn = (wid & 3) * 32;

    wmma::fragment<wmma::accumulator, 16, 16, 8, float> acc[4][2];
#pragma unroll
    for (int i = 0; i < 4; i++)
#pragma unroll
        for (int j = 0; j < 2; j++) wmma::fill_fragment(acc[i][j], 0.0f);

    const int NK = K / 32;

    // A: 128x32 = 1024 float4, 4/thread.  B: 32x128 = 1024 float4, 4/thread.
    auto load_stage = [&](int kc, int buf) {
        int k0 = kc * 32;
#pragma unroll
        for (int l = 0; l < 4; l++) {
            int f = tid + l * 256;
            int r = f >> 3, c = (f & 7) * 4;
            cp16((uint32_t)__cvta_generic_to_shared(As + buf * GA_SZ + r * GA_LD + c),
                 A + (m0 + r) * (size_t)K + k0 + c);
        }
#pragma unroll
        for (int l = 0; l < 4; l++) {
            int f = tid + l * 256;
            int r = f >> 5, c = (f & 31) * 4;
            cp16((uint32_t)__cvta_generic_to_shared(Bs + buf * GB_SZ + r * GB_LD + c),
                 B + (size_t)(k0 + r) * N + n0 + c);
        }
    };

    load_stage(0, 0);
    CP_COMMIT();

    for (int kc = 0; kc < NK; kc++) {
        int buf = kc & 1;
        if (kc + 1 < NK) { load_stage(kc + 1, buf ^ 1); CP_COMMIT(); CP_WAIT1(); }
        else            { CP_WAIT0(); }
        __syncthreads();
#pragma unroll
        for (int kk = 0; kk < 32; kk += 8) {
            wmma::fragment<wmma::matrix_a, 16, 16, 8, wmma::precision::tf32, wmma::row_major> af[4];
            wmma::fragment<wmma::matrix_b, 16, 16, 8, wmma::precision::tf32, wmma::row_major> bf[2];
#pragma unroll
            for (int i = 0; i < 4; i++)
                wmma::load_matrix_sync(af[i], As + buf * GA_SZ + (wm + 16 * i) * GA_LD + kk, GA_LD);
#pragma unroll
            for (int j = 0; j < 2; j++)
                wmma::load_matrix_sync(bf[j], Bs + buf * GB_SZ + kk * GB_LD + wn + 16 * j, GB_LD);
#pragma unroll
            for (int i = 0; i < 4; i++)
#pragma unroll
                for (int j = 0; j < 2; j++) wmma::mma_sync(acc[i][j], af[i], bf[j], acc[i][j]);
        }
        __syncthreads();
    }
#pragma unroll
    for (int i = 0; i < 4; i++)
#pragma unroll
        for (int j = 0; j < 2; j++)
            wmma::store_matrix_sync(C + (m0 + wm + 16 * i) * (size_t)N + n0 + wn + 16 * j,
                                    acc[i][j], N, wmma::mem_row_major);
}

// ---------------- LayerNorm(+bias,+one-hot) + ReLU, tf32-RN output ----------------
__global__ void __launch_bounds__(128) ln_relu_kernel(
    const float* __restrict__ in, float* __restrict__ out,
    const float* __restrict__ addb,
    const float* __restrict__ lns, const float* __restrict__ lnb,
    const float* __restrict__ w_oh, const int* __restrict__ acts)
{
    const int row = blockIdx.x;
    const int tid = threadIdx.x;
    const float* ip = in + (size_t)row * HID;

    float4 v = *(const float4*)(ip + tid * 4);
    float4 a = *(const float4*)(addb + tid * 4);
    v.x += a.x; v.y += a.y; v.z += a.z; v.w += a.w;
    if (w_oh) {
        const float* oh = w_oh + (size_t)(512 + acts[row]) * HID;
        float4 o = *(const float4*)(oh + tid * 4);
        v.x += o.x; v.y += o.y; v.z += o.z; v.w += o.w;
    }
    float sum = v.x + v.y + v.z + v.w;
    float sq  = v.x * v.x + v.y * v.y + v.z * v.z + v.w * v.w;

    __shared__ float red[8];
#pragma unroll
    for (int off = 16; off > 0; off >>= 1) {
        sum += __shfl_down_sync(0xFFFFFFFFu, sum, off);
        sq  += __shfl_down_sync(0xFFFFFFFFu, sq,  off);
    }
    if ((tid & 31) == 0) { red[tid >> 5] = sum; red[4 + (tid >> 5)] = sq; }
    __syncthreads();
    float ts = red[0] + red[1] + red[2] + red[3];
    float tq = red[4] + red[5] + red[6] + red[7];
    float mean = ts * (1.0f / HID);
    float var  = tq * (1.0f / HID) - mean * mean;
    float inv  = rsqrtf(var + 1e-6f);

    float4 sc = *(const float4*)(lns + tid * 4);
    float4 bb = *(const float4*)(lnb + tid * 4);
    float4 r;
    r.x = tf32r(fmaxf((v.x - mean) * inv * sc.x + bb.x, 0.0f));
    r.y = tf32r(fmaxf((v.y - mean) * inv * sc.y + bb.y, 0.0f));
    r.z = tf32r(fmaxf((v.z - mean) * inv * sc.z + bb.z, 0.0f));
    r.w = tf32r(fmaxf((v.w - mean) * inv * sc.w + bb.w, 0.0f));
    *(float4*)(out + (size_t)row * HID + tid * 4) = r;
}

// ---------------- initial done-mask ----------------
__global__ void mask0_kernel(const float* __restrict__ hidden_in,
                             const int* __restrict__ dones)
{
    int i = blockIdx.x * blockDim.x + threadIdx.x;
    int b = i >> 9;
    float v = dones[b] ? 0.0f : hidden_in[i];
    g_h[i] = v;
    g_htf[i] = tf32r(v);
}

// ---------------- persistent fused GRU scan (BK=32 mainloop) ----------------
__device__ __forceinline__ void gsync() {
    __threadfence();
    __syncthreads();
    if (threadIdx.x == 0) {
        unsigned int old = atomicAdd(&g_bar, 1u);
        unsigned int target = (old / SC_CTAS + 1u) * SC_CTAS;
        while (*((volatile unsigned int*)&g_bar) < target) { }
        __threadfence();
    }
    __syncthreads();
}

#define SA_LD 36
#define SA_SZ (128 * SA_LD)

__global__ void __launch_bounds__(256, 1) scan_kernel(
    const float* __restrict__ w_hr, const float* __restrict__ w_hz, const float* __restrict__ w_hn,
    const float* __restrict__ b_ir, const float* __restrict__ b_iz,
    const float* __restrict__ b_in, const float* __restrict__ b_hn,
    const int* __restrict__ dones,
    float* __restrict__ out_hidden)
{
    extern __shared__ float ssm[];
    float* Wp = ssm;                      // 3 * 512 * 20
    float* At = ssm + 3 * 512 * 20;       // 2 * SA_SZ
    float* Sc = At + 2 * SA_SZ;           // 128 * 52

    const int tid  = threadIdx.x;
    const int wid  = tid >> 5;
    const int lane = tid & 31;
    const int bx   = blockIdx.x;
    const int c0   = (bx & 31) * 16;
    const int m0   = (bx >> 5) * 128;

    // prologue: load 3 weight panels [512 x 16] as tf32-RN
    {
        const float* Ws[3] = {w_hr, w_hz, w_hn};
#pragma unroll
        for (int g = 0; g < 3; g++) {
            for (int i4 = tid; i4 < 2048; i4 += 256) {
                int k = i4 >> 2, cc = (i4 & 3) * 4;
                float4 v = *(const float4*)(Ws[g] + (size_t)k * HID + c0 + cc);
                float* d = Wp + g * (512 * 20) + k * 20 + cc;
                d[0] = tf32r(v.x); d[1] = tf32r(v.y); d[2] = tf32r(v.z); d[3] = tf32r(v.w);
            }
        }
    }
    __syncthreads();

    const int wrow = wid * 16;

    // A chunk: 128 rows x 32 cols = 1024 float4, 4/thread
    auto load_chunk = [&](int k0, int buf) {
#pragma unroll
        for (int l = 0; l < 4; l++) {
            int f = tid + l * 256;
            int r = f >> 3, c = (f & 7) * 4;
            cp16((uint32_t)__cvta_generic_to_shared(At + buf * SA_SZ + r * SA_LD + c),
                 g_htf + (size_t)(m0 + r) * HID + k0 + c);
        }
    };

    for (int t = 0; t < T_STEPS; t++) {
        wmma::fragment<wmma::accumulator, 16, 16, 8, float> acc[3];
#pragma unroll
        for (int g = 0; g < 3; g++) wmma::fill_fragment(acc[g], 0.0f);

        load_chunk(0, 0);
        CP_COMMIT();

        for (int kc = 0; kc < 16; kc++) {
            int buf = kc & 1;
            if (kc + 1 < 16) { load_chunk((kc + 1) * 32, buf ^ 1); CP_COMMIT(); CP_WAIT1(); }
            else            { CP_WAIT0(); }
            __syncthreads();
            int k0 = kc * 32;
#pragma unroll
            for (int kk = 0; kk < 32; kk += 8) {
                wmma::fragment<wmma::matrix_a, 16, 16, 8, wmma::precision::tf32, wmma::row_major> af;
                wmma::load_matrix_sync(af, At + buf * SA_SZ + wrow * SA_LD + kk, SA_LD);
#pragma unroll
                for (int g = 0; g < 3; g++) {
                    wmma::fragment<wmma::matrix_b, 16, 16, 8, wmma::precision::tf32, wmma::row_major> bf;
                    wmma::load_matrix_sync(bf, Wp + g * (512 * 20) + (k0 + kk) * 20, 20);
                    wmma::mma_sync(acc[g], af, bf, acc[g]);
                }
            }
            __syncthreads();
        }

#pragma unroll
        for (int g = 0; g < 3; g++)
            wmma::store_matrix_sync(Sc + wrow * 52 + g * 16, acc[g], 52, wmma::mem_row_major);
        __syncwarp();

        const bool lastt = (t == T_STEPS - 1);
#pragma unroll
        for (int j = 0; j < 8; j++) {
            int e = j * 32 + lane;
            int row = e >> 4, col = e & 15;
            int bg = m0 + wrow + row;
            int cg = c0 + col;
            const float* sc = Sc + (wrow + row) * 52 + col;
            float hgr = sc[0], hgz = sc[16], hgn = sc[32];
            const float* xg = g_Xg + ((size_t)t * BATCH + bg) * NG3 + cg;
            float xr = __ldcg(xg), xz = __ldcg(xg + 512), xn = __ldcg(xg + 1024);
            float r = sigm_apx(xr + __ldg(b_ir + cg) + hgr);
            float z = sigm_apx(xz + __ldg(b_iz + cg) + hgz);
            float n = tanh_acc(xn + __ldg(b_in + cg) + r * (hgn + __ldg(b_hn + cg)));
            size_t hi = (size_t)bg * HID + cg;
            float h = g_h[hi];
            float hn = (1.0f - z) * n + z * h;
            g_S0[((size_t)t * BATCH + bg) * HID + cg] = hn;
            int dn = lastt ? 0 : dones[(t + 1) * BATCH + bg];
            float hm = dn ? 0.0f : hn;
            g_h[hi] = hm;
            g_htf[hi] = tf32r(hm);
            if (lastt) out_hidden[hi] = hn;
        }

        gsync();
    }
}

// ---------------- output head ----------------
__global__ void __launch_bounds__(256) qout_kernel(
    const float* __restrict__ w_out, const float* __restrict__ b_out,
    float* __restrict__ q)
{
    __shared__ float ws[HID * ADIM];
    for (int i = threadIdx.x; i < HID * ADIM; i += 256) ws[i] = w_out[i];
    __syncthreads();

    const size_t row = (size_t)blockIdx.x * 256 + threadIdx.x;
    const float* y = g_S0 + row * HID;
    float acc[ADIM];
#pragma unroll
    for (int a = 0; a < ADIM; a++) acc[a] = b_out[a];

    for (int c = 0; c < HID; c += 4) {
        float4 v = *(const float4*)(y + c);
        float yv[4] = {v.x, v.y, v.z, v.w};
#pragma unroll
        for (int j = 0; j < 4; j++)
#pragma unroll
            for (int a = 0; a < ADIM; a++)
                acc[a] = fmaf(yv[j], ws[(c + j) * ADIM + a], acc[a]);
    }
    float* qp = q + row * ADIM;
#pragma unroll
    for (int a = 0; a < ADIM; a++) qp[a] = acc[a];
}

// ---------------- launch ----------------
extern "C" void kernel_launch(void* const* d_in, const int* in_sizes, int n_in,
                              void* d_out, int out_size)
{
    const float* hidden    = (const float*)d_in[0];
    const float* obs       = (const float*)d_in[1];
    const int*   dones     = (const int*)d_in[2];
    const int*   last_acts = (const int*)d_in[3];
    const float* w0   = (const float*)d_in[4];
    const float* b0   = (const float*)d_in[5];
    const float* ln0s = (const float*)d_in[6];
    const float* ln0b = (const float*)d_in[7];
    const float* w1   = (const float*)d_in[8];
    const float* b1   = (const float*)d_in[9];
    const float* ln1s = (const float*)d_in[10];
    const float* ln1b = (const float*)d_in[11];
    const float* w_ir = (const float*)d_in[12];
    const float* b_ir = (const float*)d_in[13];
    const float* w_iz = (const float*)d_in[14];
    const float* b_iz = (const float*)d_in[15];
    const float* w_in = (const float*)d_in[16];
    const float* b_in = (const float*)d_in[17];
    const float* w_hr = (const float*)d_in[18];
    const float* w_hz = (const float*)d_in[19];
    const float* w_hn = (const float*)d_in[20];
    const float* b_hn = (const float*)d_in[21];
    const float* w_out = (const float*)d_in[22];
    const float* b_out = (const float*)d_in[23];

    float* out_hidden = (float*)d_out;
    float* out_q      = (float*)d_out + (size_t)BATCH * HID;

    float *S0, *S1, *Xg, *w0c, *w1c, *wgc;
    cudaGetSymbolAddress((void**)&S0,  g_S0);
    cudaGetSymbolAddress((void**)&S1,  g_S1);
    cudaGetSymbolAddress((void**)&Xg,  g_Xg);
    cudaGetSymbolAddress((void**)&w0c, g_w0c);
    cudaGetSymbolAddress((void**)&w1c, g_w1c);
    cudaGetSymbolAddress((void**)&wgc, g_wgc);

    const int gemm_smem = 2 * (GA_SZ + GB_SZ) * 4;                        // 70656 B
    const int scan_smem = (3 * 512 * 20 + 2 * SA_SZ + 128 * 52) * 4;      // 186368 B
    cudaFuncSetAttribute(gemm_db, cudaFuncAttributeMaxDynamicSharedMemorySize, gemm_smem);
    cudaFuncSetAttribute(scan_kernel, cudaFuncAttributeMaxDynamicSharedMemorySize, scan_smem);

    // ordered so the ncu -s 5 window lands on gemm_db
    conv_tf32<<<(ROWS * HID / 4 + 255) / 256, 256>>>(obs, S1, ROWS * HID / 4);
    conv_tf32<<<256, 256>>>(w0, w0c, HID * HID / 4);
    conv_gates<<<1024, 256>>>(w_ir, w_iz, w_in, wgc);
    gemm_db<<<dim3(4, 512), 256, gemm_smem>>>(S1, w0c, S0, HID, HID);     // L0
    conv_tf32<<<256, 256>>>(w1, w1c, HID * HID / 4);
    mask0_kernel<<<(BATCH * HID) / 256, 256>>>(hidden, dones);
    ln_relu_kernel<<<ROWS, 128>>>(S0, S1, b0, ln0s, ln0b, w0, last_acts);
    gemm_db<<<dim3(4, 512), 256, gemm_smem>>>(S1, w1c, S0, HID, HID);     // L1
    ln_relu_kernel<<<ROWS, 128>>>(S0, S1, b1, ln1s, ln1b, nullptr, nullptr);
    gemm_db<<<dim3(12, 512), 256, gemm_smem>>>(S1, wgc, Xg, NG3, HID);    // gates

    scan_kernel<<<SC_CTAS, 256, scan_smem>>>(w_hr, w_hz, w_hn,
                                             b_ir, b_iz, b_in, b_hn,
                                             dones, out_hidden);

    qout_kernel<<<ROWS / 256, 256>>>(w_out, b_out, out_q);
}

// round 6
// speedup vs baseline: 1.5359x; 1.0509x over previous
#include <cuda_runtime.h>
#include <cuda_bf16.h>
#include <mma.h>
#include <math.h>
#include <stdint.h>

using namespace nvcuda;

#define T_STEPS 128
#define BATCH   512
#define HID     512
#define ADIM    18
#define ROWS    (T_STEPS * BATCH)   // 65536
#define NG3     (3 * HID)           // 1536
#define SC_CTAS 128

// ---------------- scratch (static __device__, no allocs) ----------------
__device__ float g_S0[(size_t)ROWS * HID];
__device__ float g_S1[(size_t)ROWS * HID];
__device__ float g_Xg[(size_t)ROWS * NG3];
__device__ float g_h  [(size_t)BATCH * HID];   // fp32 carry (exact)
__device__ float g_htf[(size_t)BATCH * HID];   // tf32-RN shadow (GEMM A operand)
__device__ float g_w0c[HID * HID];
__device__ float g_w1c[HID * HID];
__device__ float g_wgc[HID * NG3];
__device__ unsigned int g_bar;                 // monotonic grid barrier

// ---------------- cp.async helpers ----------------
__device__ __forceinline__ void cp16(uint32_t dst, const void* src) {
    asm volatile("cp.async.cg.shared.global [%0], [%1], 16;" :: "r"(dst), "l"(src));
}
#define CP_COMMIT() asm volatile("cp.async.commit_group;")
#define CP_WAIT0()  asm volatile("cp.async.wait_group 0;")
#define CP_WAIT1()  asm volatile("cp.async.wait_group 1;")

__device__ __forceinline__ float tf32r(float x) { return wmma::__float_to_tf32(x); }

__device__ __forceinline__ float tanh_apx(float x) {
    float y;
    asm("tanh.approx.f32 %0, %1;" : "=f"(y) : "f"(x));
    return y;
}
__device__ __forceinline__ float sigm_apx(float x) {
    return 0.5f * tanh_apx(0.5f * x) + 0.5f;
}
__device__ __forceinline__ float tanh_acc(float v) {
    float e2 = __expf(2.0f * v);
    return 1.0f - __fdividef(2.0f, 1.0f + e2);
}

// ---------------- tf32-RN conversion passes ----------------
__global__ void conv_tf32(const float* __restrict__ s, float* __restrict__ d, int n4) {
    int i = blockIdx.x * 256 + threadIdx.x;
    if (i < n4) {
        float4 v = ((const float4*)s)[i];
        v.x = tf32r(v.x); v.y = tf32r(v.y); v.z = tf32r(v.z); v.w = tf32r(v.w);
        ((float4*)d)[i] = v;
    }
}

// interleave [w_ir | w_iz | w_in] column-wise into [512,1536] tf32
__global__ void conv_gates(const float* __restrict__ wir, const float* __restrict__ wiz,
                           const float* __restrict__ win, float* __restrict__ dst) {
    int i = blockIdx.x * 256 + threadIdx.x;   // 262144
    int k = i >> 9, c = i & 511;
    size_t o = (size_t)k * NG3 + c;
    dst[o]        = tf32r(wir[i]);
    dst[o + 512]  = tf32r(wiz[i]);
    dst[o + 1024] = tf32r(win[i]);
}

// ---------------- 3-stage TF32 GEMM: BM=128 BN=128 BK=32 ----------------
#define GA_LD 36
#define GB_LD 132
#define GA_SZ (128 * GA_LD)       // 4608 floats / stage
#define GB_SZ (32 * GB_LD)        // 4224 floats / stage

__global__ void __launch_bounds__(256, 2) gemm_db(
    const float* __restrict__ A, const float* __restrict__ B,
    float* __restrict__ C, int N, int K)
{
    extern __shared__ float sm[];
    float* As = sm;                         // 3 stages x GA_SZ
    float* Bs = sm + 3 * GA_SZ;             // 3 stages x GB_SZ

    const int tid = threadIdx.x;
    const int wid = tid >> 5;
    const size_t m0 = (size_t)blockIdx.y * 128;
    const int n0 = blockIdx.x * 128;
    const int wm = (wid >> 2) * 64;
    const int wn = (wid & 3) * 32;

    wmma::fragment<wmma::accumulator, 16, 16, 8, float> acc[4][2];
#pragma unroll
    for (int i = 0; i < 4; i++)
#pragma unroll
        for (int j = 0; j < 2; j++) wmma::fill_fragment(acc[i][j], 0.0f);

    const int NK = K / 32;

    auto load_stage = [&](int kc, int buf) {
        int k0 = kc * 32;
#pragma unroll
        for (int l = 0; l < 4; l++) {
            int f = tid + l * 256;
            int r = f >> 3, c = (f & 7) * 4;
            cp16((uint32_t)__cvta_generic_to_shared(As + buf * GA_SZ + r * GA_LD + c),
                 A + (m0 + r) * (size_t)K + k0 + c);
        }
#pragma unroll
        for (int l = 0; l < 4; l++) {
            int f = tid + l * 256;
            int r = f >> 5, c = (f & 31) * 4;
            cp16((uint32_t)__cvta_generic_to_shared(Bs + buf * GB_SZ + r * GB_LD + c),
                 B + (size_t)(k0 + r) * N + n0 + c);
        }
    };

    load_stage(0, 0); CP_COMMIT();
    load_stage(1, 1); CP_COMMIT();

    for (int kc = 0; kc < NK; kc++) {
        int buf = kc % 3;
        if (kc + 1 < NK) CP_WAIT1(); else CP_WAIT0();
        __syncthreads();
        if (kc + 2 < NK) { load_stage(kc + 2, (kc + 2) % 3); CP_COMMIT(); }
#pragma unroll
        for (int kk = 0; kk < 32; kk += 8) {
            wmma::fragment<wmma::matrix_a, 16, 16, 8, wmma::precision::tf32, wmma::row_major> af[4];
            wmma::fragment<wmma::matrix_b, 16, 16, 8, wmma::precision::tf32, wmma::row_major> bf[2];
#pragma unroll
            for (int i = 0; i < 4; i++)
                wmma::load_matrix_sync(af[i], As + buf * GA_SZ + (wm + 16 * i) * GA_LD + kk, GA_LD);
#pragma unroll
            for (int j = 0; j < 2; j++)
                wmma::load_matrix_sync(bf[j], Bs + buf * GB_SZ + kk * GB_LD + wn + 16 * j, GB_LD);
#pragma unroll
            for (int i = 0; i < 4; i++)
#pragma unroll
                for (int j = 0; j < 2; j++) wmma::mma_sync(acc[i][j], af[i], bf[j], acc[i][j]);
        }
    }
    __syncthreads();
#pragma unroll
    for (int i = 0; i < 4; i++)
#pragma unroll
        for (int j = 0; j < 2; j++)
            wmma::store_matrix_sync(C + (m0 + wm + 16 * i) * (size_t)N + n0 + wn + 16 * j,
                                    acc[i][j], N, wmma::mem_row_major);
}

// ---------------- LayerNorm(+bias,+one-hot) + ReLU, tf32-RN output ----------------
__global__ void __launch_bounds__(128) ln_relu_kernel(
    const float* __restrict__ in, float* __restrict__ out,
    const float* __restrict__ addb,
    const float* __restrict__ lns, const float* __restrict__ lnb,
    const float* __restrict__ w_oh, const int* __restrict__ acts)
{
    const int row = blockIdx.x;
    const int tid = threadIdx.x;
    const float* ip = in + (size_t)row * HID;

    float4 v = *(const float4*)(ip + tid * 4);
    float4 a = *(const float4*)(addb + tid * 4);
    v.x += a.x; v.y += a.y; v.z += a.z; v.w += a.w;
    if (w_oh) {
        const float* oh = w_oh + (size_t)(512 + acts[row]) * HID;
        float4 o = *(const float4*)(oh + tid * 4);
        v.x += o.x; v.y += o.y; v.z += o.z; v.w += o.w;
    }
    float sum = v.x + v.y + v.z + v.w;
    float sq  = v.x * v.x + v.y * v.y + v.z * v.z + v.w * v.w;

    __shared__ float red[8];
#pragma unroll
    for (int off = 16; off > 0; off >>= 1) {
        sum += __shfl_down_sync(0xFFFFFFFFu, sum, off);
        sq  += __shfl_down_sync(0xFFFFFFFFu, sq,  off);
    }
    if ((tid & 31) == 0) { red[tid >> 5] = sum; red[4 + (tid >> 5)] = sq; }
    __syncthreads();
    float ts = red[0] + red[1] + red[2] + red[3];
    float tq = red[4] + red[5] + red[6] + red[7];
    float mean = ts * (1.0f / HID);
    float var  = tq * (1.0f / HID) - mean * mean;
    float inv  = rsqrtf(var + 1e-6f);

    float4 sc = *(const float4*)(lns + tid * 4);
    float4 bb = *(const float4*)(lnb + tid * 4);
    float4 r;
    r.x = tf32r(fmaxf((v.x - mean) * inv * sc.x + bb.x, 0.0f));
    r.y = tf32r(fmaxf((v.y - mean) * inv * sc.y + bb.y, 0.0f));
    r.z = tf32r(fmaxf((v.z - mean) * inv * sc.z + bb.z, 0.0f));
    r.w = tf32r(fmaxf((v.w - mean) * inv * sc.w + bb.w, 0.0f));
    *(float4*)(out + (size_t)row * HID + tid * 4) = r;
}

// ---------------- initial done-mask ----------------
__global__ void mask0_kernel(const float* __restrict__ hidden_in,
                             const int* __restrict__ dones)
{
    int i = blockIdx.x * blockDim.x + threadIdx.x;
    int b = i >> 9;
    float v = dones[b] ? 0.0f : hidden_in[i];
    g_h[i] = v;
    g_htf[i] = tf32r(v);
}

// ---------------- persistent fused GRU scan ----------------
__device__ __forceinline__ void gsync() {
    __threadfence();
    __syncthreads();
    if (threadIdx.x == 0) {
        unsigned int old = atomicAdd(&g_bar, 1u);
        unsigned int target = (old / SC_CTAS + 1u) * SC_CTAS;
        while (*((volatile unsigned int*)&g_bar) < target) { }
        __threadfence();
    }
    __syncthreads();
}

#define SA_LD 36
#define SA_SZ (128 * SA_LD)

__global__ void __launch_bounds__(256, 1) scan_kernel(
    const float* __restrict__ w_hr, const float* __restrict__ w_hz, const float* __restrict__ w_hn,
    const float* __restrict__ b_ir, const float* __restrict__ b_iz,
    const float* __restrict__ b_in, const float* __restrict__ b_hn,
    const int* __restrict__ dones,
    float* __restrict__ out_hidden)
{
    extern __shared__ float ssm[];
    float* Wp = ssm;                      // 3 * 512 * 20      = 30720
    float* At = Wp + 3 * 512 * 20;        // 3 * SA_SZ         = 13824
    float* Sc = At + 3 * SA_SZ;           // 128 * 52          = 6656
    float* Bb = Sc + 128 * 52;            // 4 * 16            = 64

    const int tid  = threadIdx.x;
    const int wid  = tid >> 5;
    const int lane = tid & 31;
    const int bx   = blockIdx.x;
    const int c0   = (bx & 31) * 16;
    const int m0   = (bx >> 5) * 128;

    // prologue: weight panels [512 x 16] x3 as tf32-RN + bias slices
    {
        const float* Ws[3] = {w_hr, w_hz, w_hn};
#pragma unroll
        for (int g = 0; g < 3; g++) {
            for (int i4 = tid; i4 < 2048; i4 += 256) {
                int k = i4 >> 2, cc = (i4 & 3) * 4;
                float4 v = *(const float4*)(Ws[g] + (size_t)k * HID + c0 + cc);
                float* d = Wp + g * (512 * 20) + k * 20 + cc;
                d[0] = tf32r(v.x); d[1] = tf32r(v.y); d[2] = tf32r(v.z); d[3] = tf32r(v.w);
            }
        }
        if (tid < 16) {
            Bb[tid]      = b_ir[c0 + tid];
            Bb[16 + tid] = b_iz[c0 + tid];
            Bb[32 + tid] = b_in[c0 + tid];
            Bb[48 + tid] = b_hn[c0 + tid];
        }
    }
    __syncthreads();

    const int wrow = wid * 16;

    auto load_chunk = [&](int k0, int buf) {
#pragma unroll
        for (int l = 0; l < 4; l++) {
            int f = tid + l * 256;
            int r = f >> 3, c = (f & 7) * 4;
            cp16((uint32_t)__cvta_generic_to_shared(At + buf * SA_SZ + r * SA_LD + c),
                 g_htf + (size_t)(m0 + r) * HID + k0 + c);
        }
    };

    // per-thread element coords (8 elems = warp slab 16x16)
    int erow[8], ecol[8];
#pragma unroll
    for (int j = 0; j < 8; j++) { int e = j * 32 + lane; erow[j] = e >> 4; ecol[j] = e & 15; }

    for (int t = 0; t < T_STEPS; t++) {
        const bool lastt = (t == T_STEPS - 1);

        // ---- prefetch step inputs into registers (latency hidden by GEMM) ----
        float pxr[8], pxz[8], pxn[8], ph[8];
        int pdn[8];
#pragma unroll
        for (int j = 0; j < 8; j++) {
            int bg = m0 + wrow + erow[j];
            int cg = c0 + ecol[j];
            const float* xg = g_Xg + ((size_t)t * BATCH + bg) * NG3 + cg;
            pxr[j] = __ldcg(xg);
            pxz[j] = __ldcg(xg + 512);
            pxn[j] = __ldcg(xg + 1024);
            ph[j]  = g_h[(size_t)bg * HID + cg];
            pdn[j] = lastt ? 0 : dones[(t + 1) * BATCH + bg];
        }

        // ---- GEMM: Hg_local[128 x 48] = htf[m0:,:] @ Wp (3-stage pipeline) ----
        wmma::fragment<wmma::accumulator, 16, 16, 8, float> acc[3];
#pragma unroll
        for (int g = 0; g < 3; g++) wmma::fill_fragment(acc[g], 0.0f);

        load_chunk(0, 0); CP_COMMIT();
        load_chunk(32, 1); CP_COMMIT();

        for (int kc = 0; kc < 16; kc++) {
            int buf = kc % 3;
            if (kc + 1 < 16) CP_WAIT1(); else CP_WAIT0();
            __syncthreads();
            if (kc + 2 < 16) { load_chunk((kc + 2) * 32, (kc + 2) % 3); CP_COMMIT(); }
            int k0 = kc * 32;
#pragma unroll
            for (int kk = 0; kk < 32; kk += 8) {
                wmma::fragment<wmma::matrix_a, 16, 16, 8, wmma::precision::tf32, wmma::row_major> af;
                wmma::load_matrix_sync(af, At + buf * SA_SZ + wrow * SA_LD + kk, SA_LD);
#pragma unroll
                for (int g = 0; g < 3; g++) {
                    wmma::fragment<wmma::matrix_b, 16, 16, 8, wmma::precision::tf32, wmma::row_major> bf;
                    wmma::load_matrix_sync(bf, Wp + g * (512 * 20) + (k0 + kk) * 20, 20);
                    wmma::mma_sync(acc[g], af, bf, acc[g]);
                }
            }
        }

#pragma unroll
        for (int g = 0; g < 3; g++)
            wmma::store_matrix_sync(Sc + wrow * 52 + g * 16, acc[g], 52, wmma::mem_row_major);
        __syncwarp();

        // ---- gates: pure local math ----
#pragma unroll
        for (int j = 0; j < 8; j++) {
            int bg = m0 + wrow + erow[j];
            int cg = c0 + ecol[j];
            const float* sc = Sc + (wrow + erow[j]) * 52 + ecol[j];
            float hgr = sc[0], hgz = sc[16], hgn = sc[32];
            float r = sigm_apx(pxr[j] + Bb[ecol[j]]      + hgr);
            float z = sigm_apx(pxz[j] + Bb[16 + ecol[j]] + hgz);
            float n = tanh_acc(pxn[j] + Bb[32 + ecol[j]] + r * (hgn + Bb[48 + ecol[j]]));
            float hn = (1.0f - z) * n + z * ph[j];
            size_t hi = (size_t)bg * HID + cg;
            g_S0[((size_t)t * BATCH + bg) * HID + cg] = hn;
            float hm = pdn[j] ? 0.0f : hn;
            g_h[hi] = hm;
            g_htf[hi] = tf32r(hm);
            if (lastt) out_hidden[hi] = hn;
        }

        gsync();
    }
}

// ---------------- output head ----------------
__global__ void __launch_bounds__(256) qout_kernel(
    const float* __restrict__ w_out, const float* __restrict__ b_out,
    float* __restrict__ q)
{
    __shared__ float ws[HID * ADIM];
    for (int i = threadIdx.x; i < HID * ADIM; i += 256) ws[i] = w_out[i];
    __syncthreads();

    const size_t row = (size_t)blockIdx.x * 256 + threadIdx.x;
    const float* y = g_S0 + row * HID;
    float acc[ADIM];
#pragma unroll
    for (int a = 0; a < ADIM; a++) acc[a] = b_out[a];

    for (int c = 0; c < HID; c += 4) {
        float4 v = *(const float4*)(y + c);
        float yv[4] = {v.x, v.y, v.z, v.w};
#pragma unroll
        for (int j = 0; j < 4; j++)
#pragma unroll
            for (int a = 0; a < ADIM; a++)
                acc[a] = fmaf(yv[j], ws[(c + j) * ADIM + a], acc[a]);
    }
    float* qp = q + row * ADIM;
#pragma unroll
    for (int a = 0; a < ADIM; a++) qp[a] = acc[a];
}

// ---------------- launch ----------------
extern "C" void kernel_launch(void* const* d_in, const int* in_sizes, int n_in,
                              void* d_out, int out_size)
{
    const float* hidden    = (const float*)d_in[0];
    const float* obs       = (const float*)d_in[1];
    const int*   dones     = (const int*)d_in[2];
    const int*   last_acts = (const int*)d_in[3];
    const float* w0   = (const float*)d_in[4];
    const float* b0   = (const float*)d_in[5];
    const float* ln0s = (const float*)d_in[6];
    const float* ln0b = (const float*)d_in[7];
    const float* w1   = (const float*)d_in[8];
    const float* b1   = (const float*)d_in[9];
    const float* ln1s = (const float*)d_in[10];
    const float* ln1b = (const float*)d_in[11];
    const float* w_ir = (const float*)d_in[12];
    const float* b_ir = (const float*)d_in[13];
    const float* w_iz = (const float*)d_in[14];
    const float* b_iz = (const float*)d_in[15];
    const float* w_in = (const float*)d_in[16];
    const float* b_in = (const float*)d_in[17];
    const float* w_hr = (const float*)d_in[18];
    const float* w_hz = (const float*)d_in[19];
    const float* w_hn = (const float*)d_in[20];
    const float* b_hn = (const float*)d_in[21];
    const float* w_out = (const float*)d_in[22];
    const float* b_out = (const float*)d_in[23];

    float* out_hidden = (float*)d_out;
    float* out_q      = (float*)d_out + (size_t)BATCH * HID;

    float *S0, *S1, *Xg, *w0c, *w1c, *wgc;
    cudaGetSymbolAddress((void**)&S0,  g_S0);
    cudaGetSymbolAddress((void**)&S1,  g_S1);
    cudaGetSymbolAddress((void**)&Xg,  g_Xg);
    cudaGetSymbolAddress((void**)&w0c, g_w0c);
    cudaGetSymbolAddress((void**)&w1c, g_w1c);
    cudaGetSymbolAddress((void**)&wgc, g_wgc);

    const int gemm_smem = 3 * (GA_SZ + GB_SZ) * 4;                              // 105984 B
    const int scan_smem = (3 * 512 * 20 + 3 * SA_SZ + 128 * 52 + 64) * 4;       // 205056 B
    cudaFuncSetAttribute(gemm_db, cudaFuncAttributeMaxDynamicSharedMemorySize, gemm_smem);
    cudaFuncSetAttribute(scan_kernel, cudaFuncAttributeMaxDynamicSharedMemorySize, scan_smem);

    // ordered so the ncu -s 5 window lands on gemm_db
    conv_tf32<<<(ROWS * HID / 4 + 255) / 256, 256>>>(obs, S1, ROWS * HID / 4);
    conv_tf32<<<256, 256>>>(w0, w0c, HID * HID / 4);
    conv_gates<<<1024, 256>>>(w_ir, w_iz, w_in, wgc);
    gemm_db<<<dim3(4, 512), 256, gemm_smem>>>(S1, w0c, S0, HID, HID);     // L0
    conv_tf32<<<256, 256>>>(w1, w1c, HID * HID / 4);
    mask0_kernel<<<(BATCH * HID) / 256, 256>>>(hidden, dones);
    ln_relu_kernel<<<ROWS, 128>>>(S0, S1, b0, ln0s, ln0b, w0, last_acts);
    gemm_db<<<dim3(4, 512), 256, gemm_smem>>>(S1, w1c, S0, HID, HID);     // L1
    ln_relu_kernel<<<ROWS, 128>>>(S0, S1, b1, ln1s, ln1b, nullptr, nullptr);
    gemm_db<<<dim3(12, 512), 256, gemm_smem>>>(S1, wgc, Xg, NG3, HID);    // gates

    scan_kernel<<<SC_CTAS, 256, scan_smem>>>(w_hr, w_hz, w_hn,
                                             b_ir, b_iz, b_in, b_hn,
                                             dones, out_hidden);

    qout_kernel<<<ROWS / 256, 256>>>(w_out, b_out, out_q);
}